// round 14
// baseline (speedup 1.0000x reference)
#include <cuda_runtime.h>
#include <cuda_bf16.h>
#include <cstdint>

// NeuralODE fused RK4, bf16 mma.sync m16n8k16, M=32 rows/warp, 10 warps/CTA.
// Paired-tile LDS.128 B-fragments: each 16B load feeds 4 MMAs (2 n-tiles x 2 m-tiles).
// RK4 state (y0, rk4) in SMEM float4 fragment order (conflict-free, no padding).
// Zero syncs in the main loop.

#define D_IN      64
#define HID       256
#define NT        320
#define NWARPS    10
#define BLK_ROWS  (NWARPS * 32)   // 320
#define NSTEPS    64
#define TOTAL_ROWS 262144
#define GRID      820             // ceil(262144 / 320); tail CTA: 2 active warps

// SMEM (bytes)
#define W1F_OFF   0        // u32[8192] paired-tile blocks (32KB)
#define W2F_OFF   32768    // u32[8192] (32KB)
#define B1_OFF    65536    // float[256]
#define B2_OFF    66560    // float[64]
#define ST_OFF    66816    // state: 10 warps x 16384B (y0 8KB | rk4 8KB)
#define SMEM_BYTES (66816 + NWARPS * 16384)   // 230656

__device__ __forceinline__ uint32_t pack_bf16(float lo, float hi) {
    uint32_t r;
    asm("cvt.rn.bf16x2.f32 %0, %1, %2;" : "=r"(r) : "f"(hi), "f"(lo));
    return r;
}

__device__ __forceinline__ void mma_bf16(float c[4],
                                         uint32_t a0, uint32_t a1, uint32_t a2, uint32_t a3,
                                         uint32_t b0, uint32_t b1) {
    asm volatile(
        "mma.sync.aligned.m16n8k16.row.col.f32.bf16.bf16.f32 "
        "{%0,%1,%2,%3}, {%4,%5,%6,%7}, {%8,%9}, {%0,%1,%2,%3};\n"
        : "+f"(c[0]), "+f"(c[1]), "+f"(c[2]), "+f"(c[3])
        : "r"(a0), "r"(a1), "r"(a2), "r"(a3), "r"(b0), "r"(b1));
}

__device__ __forceinline__ float elu_f(float v) {
    float e = __expf(v) - 1.0f;
    return v > 0.0f ? v : e;
}

__global__ void __launch_bounds__(NT, 1)
node_rk4_m32p_kernel(const float* __restrict__ x,
                     const float* __restrict__ tptr,
                     const float* __restrict__ W1,   // [256,64] row-major
                     const float* __restrict__ b1,   // [256]
                     const float* __restrict__ W2,   // [64,256] row-major
                     const float* __restrict__ b2,   // [64]
                     float* __restrict__ out) {
    extern __shared__ char smem_c[];
    uint32_t* W1f = (uint32_t*)(smem_c + W1F_OFF);
    uint32_t* W2f = (uint32_t*)(smem_c + W2F_OFF);
    float*    b1s = (float*)(smem_c + B1_OFF);
    float*    b2s = (float*)(smem_c + B2_OFF);

    const int tid  = threadIdx.x;
    const int lane = tid & 31;
    const int warp = tid >> 5;
    const int g    = lane >> 2;
    const int tq   = lane & 3;

    // ---- W1 B-fragments, paired-tile blocks ----
    // block = nc*4 + kt (nc 0..15, kt 0..3); 128 u32/block; slot = blk*128 + ln*4 + q.
    // q = (o<<1)|j; tile nt = nc*2 + o; n = nt*8 + (ln>>2); k = kt*16 + 2*(ln&3) + j*8.
    for (int i = tid; i < 8192; i += NT) {
        int q = i & 3, ln = (i >> 2) & 31, blk = i >> 7;
        int kt = blk & 3, nc = blk >> 2;
        int o = q >> 1, j = q & 1;
        int n = (nc * 2 + o) * 8 + (ln >> 2);
        int k = kt * 16 + 2 * (ln & 3) + (j ? 8 : 0);
        const float2 w = *(const float2*)(W1 + n * D_IN + k);
        W1f[i] = pack_bf16(w.x, w.y);
    }
    // ---- W2 B-fragments, paired-tile blocks ----
    // block = nc*4 + n2p (nc = k2-tile 0..15, n2p 0..3); tile nt2 = n2p*2 + o;
    // n = nt2*8 + (ln>>2); k = nc*16 + 2*(ln&3) + j*8.
    for (int i = tid; i < 8192; i += NT) {
        int q = i & 3, ln = (i >> 2) & 31, blk = i >> 7;
        int n2p = blk & 3, nc = blk >> 2;
        int o = q >> 1, j = q & 1;
        int n = (n2p * 2 + o) * 8 + (ln >> 2);
        int k = nc * 16 + 2 * (ln & 3) + (j ? 8 : 0);
        const float2 w = *(const float2*)(W2 + n * HID + k);
        W2f[i] = pack_bf16(w.x, w.y);
    }
    for (int i = tid; i < HID; i += NT) b1s[i] = b1[i];
    for (int i = tid; i < D_IN; i += NT) b2s[i] = b2[i];
    __syncthreads();

    const int rbase = blockIdx.x * BLK_ROWS + warp * 32;
    if (rbase >= TOTAL_ROWS) return;   // tail CTA: inactive warps exit

    const float t0 = tptr[0];
    const float dt = t0 * 0.015625f;
    const float half_dt = 0.5f * dt;
    const float dt6 = dt * (1.0f / 6.0f);

    // per-warp state, float4 fragment order: index (mt*8+nt)*32 + lane
    float4* y0p = (float4*)(smem_c + ST_OFF + warp * 16384) + lane;
    float4* rkp = (float4*)(smem_c + ST_OFF + warp * 16384 + 8192) + lane;

    // ---- load x: y0 -> SMEM (fragment order), pack A1 frags ----
    uint32_t a1f[32];   // [mt*16 + kt*4 + r]
#pragma unroll
    for (int mt = 0; mt < 2; ++mt) {
        const float* xr0 = x + (size_t)(rbase + mt * 16 + g) * D_IN + 2 * tq;
        const float* xr1 = x + (size_t)(rbase + mt * 16 + g + 8) * D_IN + 2 * tq;
#pragma unroll
        for (int nt = 0; nt < 8; ++nt) {
            float2 u = *(const float2*)(xr0 + nt * 8);
            float2 v = *(const float2*)(xr1 + nt * 8);
            y0p[(mt * 8 + nt) * 32] = make_float4(u.x, u.y, v.x, v.y);
            int kt = nt >> 1, r0 = (nt & 1) * 2;
            a1f[mt * 16 + kt * 4 + r0]     = pack_bf16(u.x, u.y);
            a1f[mt * 16 + kt * 4 + r0 + 1] = pack_bf16(v.x, v.y);
        }
    }

#pragma unroll 1
    for (int e = 0; e < NSTEPS * 4; ++e) {
        const int s = e & 3;

        float kacc[2][8][4];
#pragma unroll
        for (int mt = 0; mt < 2; ++mt)
#pragma unroll
            for (int nt = 0; nt < 8; ++nt)
#pragma unroll
                for (int j = 0; j < 4; ++j) kacc[mt][nt][j] = 0.0f;

#pragma unroll 4
        for (int nc = 0; nc < 16; ++nc) {
            // ---- GEMM1 chunk: one n-pair (16 hidden cols), K=64, both m-tiles ----
            float c1[2][2][4];
#pragma unroll
            for (int mt = 0; mt < 2; ++mt)
#pragma unroll
                for (int ntl = 0; ntl < 2; ++ntl)
#pragma unroll
                    for (int j = 0; j < 4; ++j) c1[mt][ntl][j] = 0.0f;

#pragma unroll
            for (int kt = 0; kt < 4; ++kt) {
                const uint4 b = *(const uint4*)(W1f + ((nc * 4 + kt) * 128 + lane * 4));
                mma_bf16(c1[0][0], a1f[kt * 4], a1f[kt * 4 + 1], a1f[kt * 4 + 2], a1f[kt * 4 + 3], b.x, b.y);
                mma_bf16(c1[0][1], a1f[kt * 4], a1f[kt * 4 + 1], a1f[kt * 4 + 2], a1f[kt * 4 + 3], b.z, b.w);
                mma_bf16(c1[1][0], a1f[16 + kt * 4], a1f[16 + kt * 4 + 1], a1f[16 + kt * 4 + 2], a1f[16 + kt * 4 + 3], b.x, b.y);
                mma_bf16(c1[1][1], a1f[16 + kt * 4], a1f[16 + kt * 4 + 1], a1f[16 + kt * 4 + 2], a1f[16 + kt * 4 + 3], b.z, b.w);
            }

            // ---- bias + ELU + pack: chunk = one GEMM2 A k-tile (both m-tiles) ----
            uint32_t hf[2][4];
#pragma unroll
            for (int ntl = 0; ntl < 2; ++ntl) {
                const float2 bb = *(const float2*)(b1s + (nc * 16 + ntl * 8 + 2 * tq));
#pragma unroll
                for (int mt = 0; mt < 2; ++mt) {
                    float v00 = elu_f(c1[mt][ntl][0] + bb.x);
                    float v01 = elu_f(c1[mt][ntl][1] + bb.y);
                    float v10 = elu_f(c1[mt][ntl][2] + bb.x);
                    float v11 = elu_f(c1[mt][ntl][3] + bb.y);
                    hf[mt][ntl * 2 + 0] = pack_bf16(v00, v01);
                    hf[mt][ntl * 2 + 1] = pack_bf16(v10, v11);
                }
            }

            // ---- GEMM2 partial: k2-tile = nc, 4 n-pairs, both m-tiles ----
#pragma unroll
            for (int n2p = 0; n2p < 4; ++n2p) {
                const uint4 b = *(const uint4*)(W2f + ((nc * 4 + n2p) * 128 + lane * 4));
                mma_bf16(kacc[0][2 * n2p],     hf[0][0], hf[0][1], hf[0][2], hf[0][3], b.x, b.y);
                mma_bf16(kacc[0][2 * n2p + 1], hf[0][0], hf[0][1], hf[0][2], hf[0][3], b.z, b.w);
                mma_bf16(kacc[1][2 * n2p],     hf[1][0], hf[1][1], hf[1][2], hf[1][3], b.x, b.y);
                mma_bf16(kacc[1][2 * n2p + 1], hf[1][0], hf[1][1], hf[1][2], hf[1][3], b.z, b.w);
            }
        } // nc

        // ---- epilogue: k = kacc + b2; RK4 state in SMEM; rebuild A1 frags ----
        const float wk = (s == 1 || s == 2) ? 2.0f : 1.0f;
        const float cn = (s == 2) ? dt : half_dt;
        const bool last = (e == NSTEPS * 4 - 1);
#pragma unroll
        for (int mt = 0; mt < 2; ++mt) {
#pragma unroll
            for (int nt = 0; nt < 8; ++nt) {
                const int fo = (mt * 8 + nt) * 32;
                const float2 bb = *(const float2*)(b2s + (nt * 8 + 2 * tq));
                float k0 = kacc[mt][nt][0] + bb.x;
                float k1 = kacc[mt][nt][1] + bb.y;
                float k2 = kacc[mt][nt][2] + bb.x;
                float k3 = kacc[mt][nt][3] + bb.y;

                float4 r4;
                if (s == 0) {
                    r4 = make_float4(k0, k1, k2, k3);
                } else {
                    r4 = rkp[fo];
                    r4.x += wk * k0; r4.y += wk * k1;
                    r4.z += wk * k2; r4.w += wk * k3;
                }
                if (s < 3) rkp[fo] = r4;

                float4 y4 = y0p[fo];
                float yn0, yn1, yn2, yn3;
                if (s < 3) {
                    yn0 = y4.x + cn * k0; yn1 = y4.y + cn * k1;
                    yn2 = y4.z + cn * k2; yn3 = y4.w + cn * k3;
                } else {
                    yn0 = y4.x + dt6 * r4.x; yn1 = y4.y + dt6 * r4.y;
                    yn2 = y4.z + dt6 * r4.z; yn3 = y4.w + dt6 * r4.w;
                    if (!last) {
                        y0p[fo] = make_float4(yn0, yn1, yn2, yn3);
                    } else {
                        float* or0 = out + (size_t)(rbase + mt * 16 + g) * D_IN + nt * 8 + 2 * tq;
                        float* or1 = out + (size_t)(rbase + mt * 16 + g + 8) * D_IN + nt * 8 + 2 * tq;
                        *(float2*)or0 = make_float2(yn0, yn1);
                        *(float2*)or1 = make_float2(yn2, yn3);
                    }
                }
                int kt = nt >> 1, r0 = (nt & 1) * 2;
                a1f[mt * 16 + kt * 4 + r0]     = pack_bf16(yn0, yn1);
                a1f[mt * 16 + kt * 4 + r0 + 1] = pack_bf16(yn2, yn3);
            }
        }
    } // eval loop
}

extern "C" void kernel_launch(void* const* d_in, const int* in_sizes, int n_in,
                              void* d_out, int out_size) {
    const float* x  = (const float*)d_in[0];
    const float* t  = (const float*)d_in[1];
    const float* W1 = (const float*)d_in[2];
    const float* b1 = (const float*)d_in[3];
    const float* W2 = (const float*)d_in[4];
    const float* b2 = (const float*)d_in[5];
    float* out = (float*)d_out;

    cudaFuncSetAttribute(node_rk4_m32p_kernel,
                         cudaFuncAttributeMaxDynamicSharedMemorySize, SMEM_BYTES);
    node_rk4_m32p_kernel<<<GRID, NT, SMEM_BYTES>>>(x, t, W1, b1, W2, b2, out);
}

// round 15
// speedup vs baseline: 1.2090x; 1.2090x over previous
#include <cuda_runtime.h>
#include <cuda_bf16.h>
#include <cuda_fp16.h>
#include <cstdint>

// NeuralODE fused RK4, bf16 mma.sync m16n8k16, register-resident state.
// 14 warps/CTA x 16 rows = 224 rows/CTA (3.5 warps/SMSP). rk4 accumulator is
// packed fp16x2 (16 regs) to fit the 144-reg cap. Accumulators start at the
// bias fragments (no separate bias adds). Paired-tile LDS.128 B-fragments.
// Zero syncs / zero state traffic in the main loop.

#define D_IN      64
#define HID       256
#define NT        448
#define NWARPS    14
#define BLK_ROWS  (NWARPS * 16)   // 224
#define NSTEPS    64
#define TOTAL_ROWS 262144
#define GRID      1171            // ceil(262144 / 224); tail CTA: 4 active warps

// SMEM (bytes): W1 frags 32KB, W2 frags 32KB, b1 1KB, b2 256B
#define W1F_OFF   0        // u32[8192], paired-tile blocks of 128 u32
#define W2F_OFF   32768    // u32[8192]
#define B1_OFF    65536    // float[256]
#define B2_OFF    66560    // float[64]
#define SMEM_BYTES 66816

__device__ __forceinline__ uint32_t pack_bf16(float lo, float hi) {
    uint32_t r;
    asm("cvt.rn.bf16x2.f32 %0, %1, %2;" : "=r"(r) : "f"(hi), "f"(lo));
    return r;
}
__device__ __forceinline__ uint32_t pack_f16(float lo, float hi) {
    uint32_t r;
    asm("cvt.rn.f16x2.f32 %0, %1, %2;" : "=r"(r) : "f"(hi), "f"(lo));
    return r;
}
__device__ __forceinline__ float2 unpack_f16(uint32_t u) {
    __half2 h = *(__half2*)&u;
    return __half22float2(h);
}

__device__ __forceinline__ void mma_bf16(float c[4],
                                         uint32_t a0, uint32_t a1, uint32_t a2, uint32_t a3,
                                         uint32_t b0, uint32_t b1) {
    asm volatile(
        "mma.sync.aligned.m16n8k16.row.col.f32.bf16.bf16.f32 "
        "{%0,%1,%2,%3}, {%4,%5,%6,%7}, {%8,%9}, {%0,%1,%2,%3};\n"
        : "+f"(c[0]), "+f"(c[1]), "+f"(c[2]), "+f"(c[3])
        : "r"(a0), "r"(a1), "r"(a2), "r"(a3), "r"(b0), "r"(b1));
}

__device__ __forceinline__ float elu_f(float v) {
    float e = __expf(v) - 1.0f;
    return v > 0.0f ? v : e;
}

__global__ void __launch_bounds__(NT, 1)
node_rk4_w14_kernel(const float* __restrict__ x,
                    const float* __restrict__ tptr,
                    const float* __restrict__ W1,   // [256,64] row-major
                    const float* __restrict__ b1,   // [256]
                    const float* __restrict__ W2,   // [64,256] row-major
                    const float* __restrict__ b2,   // [64]
                    float* __restrict__ out) {
    extern __shared__ char smem_c[];
    uint32_t* W1f = (uint32_t*)(smem_c + W1F_OFF);
    uint32_t* W2f = (uint32_t*)(smem_c + W2F_OFF);
    float*    b1s = (float*)(smem_c + B1_OFF);
    float*    b2s = (float*)(smem_c + B2_OFF);

    const int tid  = threadIdx.x;
    const int lane = tid & 31;
    const int warp = tid >> 5;
    const int g    = lane >> 2;
    const int tq   = lane & 3;

    // ---- W1 B-fragments, paired-tile layout ----
    // block = (nc*2 + p)*4 + kt; 128 u32 per block; slot = blk*128 + ln*4 + q.
    // q = (o<<1)|j; tile nt = (nc*2+p)*2 + o; B1[k][n] = W1[n][k].
    for (int i = tid; i < 8192; i += NT) {
        int q = i & 3, ln = (i >> 2) & 31, blk = i >> 7;
        int kt = blk & 3, np = blk >> 2;
        int o = q >> 1, j = q & 1;
        int n = (np * 2 + o) * 8 + (ln >> 2);
        int k = kt * 16 + 2 * (ln & 3) + (j ? 8 : 0);
        const float2 w = *(const float2*)(W1 + n * D_IN + k);
        W1f[i] = pack_bf16(w.x, w.y);
    }
    // ---- W2 B-fragments, paired-tile layout ----
    // block = (nc*2 + ktl)*4 + n2p; tile nt2 = n2p*2 + o; B2[k][n] = W2[n][k].
    for (int i = tid; i < 8192; i += NT) {
        int q = i & 3, ln = (i >> 2) & 31, blk = i >> 7;
        int n2p = blk & 3, kt2 = blk >> 2;
        int o = q >> 1, j = q & 1;
        int n = (n2p * 2 + o) * 8 + (ln >> 2);
        int k = kt2 * 16 + 2 * (ln & 3) + (j ? 8 : 0);
        const float2 w = *(const float2*)(W2 + n * HID + k);
        W2f[i] = pack_bf16(w.x, w.y);
    }
    for (int i = tid; i < HID; i += NT) b1s[i] = b1[i];
    for (int i = tid; i < D_IN; i += NT) b2s[i] = b2[i];
    __syncthreads();

    const int rbase = blockIdx.x * BLK_ROWS + warp * 16;
    if (rbase >= TOTAL_ROWS) return;   // tail CTA: inactive warps exit

    const float t0 = tptr[0];
    const float dt = t0 * 0.015625f;
    const float half_dt = 0.5f * dt;
    const float dt6 = dt * (1.0f / 6.0f);

    // ---- load x in C-fragment layout ----
    float y0[8][4];
    {
        const float* xr0 = x + (size_t)(rbase + g) * D_IN + 2 * tq;
        const float* xr1 = x + (size_t)(rbase + g + 8) * D_IN + 2 * tq;
#pragma unroll
        for (int nt = 0; nt < 8; ++nt) {
            float2 u = *(const float2*)(xr0 + nt * 8);
            float2 v = *(const float2*)(xr1 + nt * 8);
            y0[nt][0] = u.x; y0[nt][1] = u.y;
            y0[nt][2] = v.x; y0[nt][3] = v.y;
        }
    }

    uint32_t a1f[16];   // A1 frags of y: [kt*4 + r]
#pragma unroll
    for (int kt = 0; kt < 4; ++kt) {
        a1f[kt * 4 + 0] = pack_bf16(y0[2 * kt][0],     y0[2 * kt][1]);
        a1f[kt * 4 + 1] = pack_bf16(y0[2 * kt][2],     y0[2 * kt][3]);
        a1f[kt * 4 + 2] = pack_bf16(y0[2 * kt + 1][0], y0[2 * kt + 1][1]);
        a1f[kt * 4 + 3] = pack_bf16(y0[2 * kt + 1][2], y0[2 * kt + 1][3]);
    }

    uint32_t rk4h[16];  // rk4 accumulator, fp16x2: [nt*2 + {01,23}]

#pragma unroll 1
    for (int e = 0; e < NSTEPS * 4; ++e) {
        const int s = e & 3;

        // kacc initialized to b2 bias fragments (GEMM2 accumulates onto bias)
        float kacc[8][4];
#pragma unroll
        for (int nt = 0; nt < 8; ++nt) {
            const float2 bb = *(const float2*)(b2s + (nt * 8 + 2 * tq));
            kacc[nt][0] = bb.x; kacc[nt][1] = bb.y;
            kacc[nt][2] = bb.x; kacc[nt][3] = bb.y;
        }

#pragma unroll
        for (int nc = 0; nc < 8; ++nc) {
            // ---- GEMM1 chunk: 4 ntiles (2 pairs), K=64; c1 starts at b1 bias ----
            float c1[4][4];
#pragma unroll
            for (int nt = 0; nt < 4; ++nt) {
                const float2 bb = *(const float2*)(b1s + (nc * 32 + nt * 8 + 2 * tq));
                c1[nt][0] = bb.x; c1[nt][1] = bb.y;
                c1[nt][2] = bb.x; c1[nt][3] = bb.y;
            }

#pragma unroll
            for (int kt = 0; kt < 4; ++kt) {
#pragma unroll
                for (int p = 0; p < 2; ++p) {
                    const uint4 b = *(const uint4*)(W1f + (((nc * 2 + p) * 4 + kt) * 128 + lane * 4));
                    mma_bf16(c1[2 * p],     a1f[kt * 4], a1f[kt * 4 + 1], a1f[kt * 4 + 2], a1f[kt * 4 + 3], b.x, b.y);
                    mma_bf16(c1[2 * p + 1], a1f[kt * 4], a1f[kt * 4 + 1], a1f[kt * 4 + 2], a1f[kt * 4 + 3], b.z, b.w);
                }
            }

            // ---- ELU + pack: C-frags -> GEMM2 A-frags in registers ----
            uint32_t hf[2][4];
#pragma unroll
            for (int nt = 0; nt < 4; ++nt) {
                float v00 = elu_f(c1[nt][0]);
                float v01 = elu_f(c1[nt][1]);
                float v10 = elu_f(c1[nt][2]);
                float v11 = elu_f(c1[nt][3]);
                hf[nt >> 1][(nt & 1) * 2 + 0] = pack_bf16(v00, v01);
                hf[nt >> 1][(nt & 1) * 2 + 1] = pack_bf16(v10, v11);
            }

            // ---- GEMM2 partial: 2 ktiles of 16, 4 n-pairs each ----
#pragma unroll
            for (int ktl = 0; ktl < 2; ++ktl) {
#pragma unroll
                for (int n2p = 0; n2p < 4; ++n2p) {
                    const uint4 b = *(const uint4*)(W2f + (((nc * 2 + ktl) * 4 + n2p) * 128 + lane * 4));
                    mma_bf16(kacc[2 * n2p],     hf[ktl][0], hf[ktl][1], hf[ktl][2], hf[ktl][3], b.x, b.y);
                    mma_bf16(kacc[2 * n2p + 1], hf[ktl][0], hf[ktl][1], hf[ktl][2], hf[ktl][3], b.z, b.w);
                }
            }
        } // nc

        // ---- epilogue: k = kacc (bias included); rk4 in fp16x2; repack A1 ----
        const float wk = (s == 1 || s == 2) ? 2.0f : 1.0f;
        const float cn = (s == 2) ? dt : half_dt;
        float yn[8][4];
#pragma unroll
        for (int nt = 0; nt < 8; ++nt) {
            float k0 = kacc[nt][0], k1 = kacc[nt][1];
            float k2 = kacc[nt][2], k3 = kacc[nt][3];

            if (s == 0) {
                rk4h[2 * nt]     = pack_f16(k0, k1);
                rk4h[2 * nt + 1] = pack_f16(k2, k3);
                yn[nt][0] = y0[nt][0] + cn * k0;
                yn[nt][1] = y0[nt][1] + cn * k1;
                yn[nt][2] = y0[nt][2] + cn * k2;
                yn[nt][3] = y0[nt][3] + cn * k3;
            } else if (s < 3) {
                float2 r01 = unpack_f16(rk4h[2 * nt]);
                float2 r23 = unpack_f16(rk4h[2 * nt + 1]);
                r01.x += wk * k0; r01.y += wk * k1;
                r23.x += wk * k2; r23.y += wk * k3;
                rk4h[2 * nt]     = pack_f16(r01.x, r01.y);
                rk4h[2 * nt + 1] = pack_f16(r23.x, r23.y);
                yn[nt][0] = y0[nt][0] + cn * k0;
                yn[nt][1] = y0[nt][1] + cn * k1;
                yn[nt][2] = y0[nt][2] + cn * k2;
                yn[nt][3] = y0[nt][3] + cn * k3;
            } else {
                float2 r01 = unpack_f16(rk4h[2 * nt]);
                float2 r23 = unpack_f16(rk4h[2 * nt + 1]);
                y0[nt][0] += dt6 * (r01.x + k0);
                y0[nt][1] += dt6 * (r01.y + k1);
                y0[nt][2] += dt6 * (r23.x + k2);
                y0[nt][3] += dt6 * (r23.y + k3);
                yn[nt][0] = y0[nt][0]; yn[nt][1] = y0[nt][1];
                yn[nt][2] = y0[nt][2]; yn[nt][3] = y0[nt][3];
            }
        }
#pragma unroll
        for (int kt = 0; kt < 4; ++kt) {
            a1f[kt * 4 + 0] = pack_bf16(yn[2 * kt][0],     yn[2 * kt][1]);
            a1f[kt * 4 + 1] = pack_bf16(yn[2 * kt][2],     yn[2 * kt][3]);
            a1f[kt * 4 + 2] = pack_bf16(yn[2 * kt + 1][0], yn[2 * kt + 1][1]);
            a1f[kt * 4 + 3] = pack_bf16(yn[2 * kt + 1][2], yn[2 * kt + 1][3]);
        }
    } // eval loop

    // ---- write final y0 ----
    {
        float* or0 = out + (size_t)(rbase + g) * D_IN + 2 * tq;
        float* or1 = out + (size_t)(rbase + g + 8) * D_IN + 2 * tq;
#pragma unroll
        for (int nt = 0; nt < 8; ++nt) {
            *(float2*)(or0 + nt * 8) = make_float2(y0[nt][0], y0[nt][1]);
            *(float2*)(or1 + nt * 8) = make_float2(y0[nt][2], y0[nt][3]);
        }
    }
}

extern "C" void kernel_launch(void* const* d_in, const int* in_sizes, int n_in,
                              void* d_out, int out_size) {
    const float* x  = (const float*)d_in[0];
    const float* t  = (const float*)d_in[1];
    const float* W1 = (const float*)d_in[2];
    const float* b1 = (const float*)d_in[3];
    const float* W2 = (const float*)d_in[4];
    const float* b2 = (const float*)d_in[5];
    float* out = (float*)d_out;

    cudaFuncSetAttribute(node_rk4_w14_kernel,
                         cudaFuncAttributeMaxDynamicSharedMemorySize, SMEM_BYTES);
    node_rk4_w14_kernel<<<GRID, NT, SMEM_BYTES>>>(x, t, W1, b1, W2, b2, out);
}

// round 17
// speedup vs baseline: 1.4946x; 1.2362x over previous
#include <cuda_runtime.h>
#include <cuda_bf16.h>
#include <cuda_fp16.h>
#include <cstdint>

// NeuralODE fused RK4, bf16 mma.sync m16n8k16, register-resident state.
// 12 warps/CTA x 16 rows (3 warps/SMSP). fp16x2 rk4 accumulator + bias-init
// accumulators free ~16 persistent regs + ~192 FADDs/eval; B-fragment loads
// are explicitly batched (MLP=4) for latency hiding. Paired-tile LDS.128.
// Zero syncs / zero state traffic in the main loop.

#define D_IN      64
#define HID       256
#define NT        384
#define NWARPS    12
#define BLK_ROWS  (NWARPS * 16)   // 192
#define NSTEPS    64
#define TOTAL_ROWS 262144
#define GRID      1366            // ceil(262144 / 192); tail CTA: 4 active warps

// SMEM (bytes): W1 frags 32KB, W2 frags 32KB, b1 1KB, b2 256B
#define W1F_OFF   0        // u32[8192], paired-tile blocks of 128 u32
#define W2F_OFF   32768    // u32[8192]
#define B1_OFF    65536    // float[256]
#define B2_OFF    66560    // float[64]
#define SMEM_BYTES 66816

__device__ __forceinline__ uint32_t pack_bf16(float lo, float hi) {
    uint32_t r;
    asm("cvt.rn.bf16x2.f32 %0, %1, %2;" : "=r"(r) : "f"(hi), "f"(lo));
    return r;
}
__device__ __forceinline__ uint32_t pack_f16(float lo, float hi) {
    uint32_t r;
    asm("cvt.rn.f16x2.f32 %0, %1, %2;" : "=r"(r) : "f"(hi), "f"(lo));
    return r;
}
__device__ __forceinline__ float2 unpack_f16(uint32_t u) {
    __half2 h = *(__half2*)&u;
    return __half22float2(h);
}

__device__ __forceinline__ void mma_bf16(float c[4],
                                         uint32_t a0, uint32_t a1, uint32_t a2, uint32_t a3,
                                         uint32_t b0, uint32_t b1) {
    asm volatile(
        "mma.sync.aligned.m16n8k16.row.col.f32.bf16.bf16.f32 "
        "{%0,%1,%2,%3}, {%4,%5,%6,%7}, {%8,%9}, {%0,%1,%2,%3};\n"
        : "+f"(c[0]), "+f"(c[1]), "+f"(c[2]), "+f"(c[3])
        : "r"(a0), "r"(a1), "r"(a2), "r"(a3), "r"(b0), "r"(b1));
}

__device__ __forceinline__ float elu_f(float v) {
    float e = __expf(v) - 1.0f;
    return v > 0.0f ? v : e;
}

__global__ void __launch_bounds__(NT, 1)
node_rk4_w12h_kernel(const float* __restrict__ x,
                     const float* __restrict__ tptr,
                     const float* __restrict__ W1,   // [256,64] row-major
                     const float* __restrict__ b1,   // [256]
                     const float* __restrict__ W2,   // [64,256] row-major
                     const float* __restrict__ b2,   // [64]
                     float* __restrict__ out) {
    extern __shared__ char smem_c[];
    uint32_t* W1f = (uint32_t*)(smem_c + W1F_OFF);
    uint32_t* W2f = (uint32_t*)(smem_c + W2F_OFF);
    float*    b1s = (float*)(smem_c + B1_OFF);
    float*    b2s = (float*)(smem_c + B2_OFF);

    const int tid  = threadIdx.x;
    const int lane = tid & 31;
    const int warp = tid >> 5;
    const int g    = lane >> 2;
    const int tq   = lane & 3;

    // ---- W1 B-fragments, paired-tile layout ----
    // block = (nc*2 + p)*4 + kt; slot = blk*128 + ln*4 + q; q = (o<<1)|j;
    // tile nt = (nc*2+p)*2 + o; B1[k][n] = W1[n][k].
    for (int i = tid; i < 8192; i += NT) {
        int q = i & 3, ln = (i >> 2) & 31, blk = i >> 7;
        int kt = blk & 3, np = blk >> 2;
        int o = q >> 1, j = q & 1;
        int n = (np * 2 + o) * 8 + (ln >> 2);
        int k = kt * 16 + 2 * (ln & 3) + (j ? 8 : 0);
        const float2 w = *(const float2*)(W1 + n * D_IN + k);
        W1f[i] = pack_bf16(w.x, w.y);
    }
    // ---- W2 B-fragments, paired-tile layout ----
    // block = (nc*2 + ktl)*4 + n2p; tile nt2 = n2p*2 + o; B2[k][n] = W2[n][k].
    for (int i = tid; i < 8192; i += NT) {
        int q = i & 3, ln = (i >> 2) & 31, blk = i >> 7;
        int n2p = blk & 3, kt2 = blk >> 2;
        int o = q >> 1, j = q & 1;
        int n = (n2p * 2 + o) * 8 + (ln >> 2);
        int k = kt2 * 16 + 2 * (ln & 3) + (j ? 8 : 0);
        const float2 w = *(const float2*)(W2 + n * HID + k);
        W2f[i] = pack_bf16(w.x, w.y);
    }
    for (int i = tid; i < HID; i += NT) b1s[i] = b1[i];
    for (int i = tid; i < D_IN; i += NT) b2s[i] = b2[i];
    __syncthreads();

    const int rbase = blockIdx.x * BLK_ROWS + warp * 16;
    if (rbase >= TOTAL_ROWS) return;   // tail CTA: inactive warps exit

    const float t0 = tptr[0];
    const float dt = t0 * 0.015625f;
    const float half_dt = 0.5f * dt;
    const float dt6 = dt * (1.0f / 6.0f);

    // ---- load x in C-fragment layout ----
    float y0[8][4];
    {
        const float* xr0 = x + (size_t)(rbase + g) * D_IN + 2 * tq;
        const float* xr1 = x + (size_t)(rbase + g + 8) * D_IN + 2 * tq;
#pragma unroll
        for (int nt = 0; nt < 8; ++nt) {
            float2 u = *(const float2*)(xr0 + nt * 8);
            float2 v = *(const float2*)(xr1 + nt * 8);
            y0[nt][0] = u.x; y0[nt][1] = u.y;
            y0[nt][2] = v.x; y0[nt][3] = v.y;
        }
    }

    uint32_t a1f[16];   // A1 frags of y: [kt*4 + r]
#pragma unroll
    for (int kt = 0; kt < 4; ++kt) {
        a1f[kt * 4 + 0] = pack_bf16(y0[2 * kt][0],     y0[2 * kt][1]);
        a1f[kt * 4 + 1] = pack_bf16(y0[2 * kt][2],     y0[2 * kt][3]);
        a1f[kt * 4 + 2] = pack_bf16(y0[2 * kt + 1][0], y0[2 * kt + 1][1]);
        a1f[kt * 4 + 3] = pack_bf16(y0[2 * kt + 1][2], y0[2 * kt + 1][3]);
    }

    uint32_t rk4h[16];  // rk4 accumulator, fp16x2: [nt*2 + {01,23}]

#pragma unroll 1
    for (int e = 0; e < NSTEPS * 4; ++e) {
        const int s = e & 3;

        // kacc initialized to b2 bias fragments (GEMM2 accumulates onto bias)
        float kacc[8][4];
#pragma unroll
        for (int nt = 0; nt < 8; ++nt) {
            const float2 bb = *(const float2*)(b2s + (nt * 8 + 2 * tq));
            kacc[nt][0] = bb.x; kacc[nt][1] = bb.y;
            kacc[nt][2] = bb.x; kacc[nt][3] = bb.y;
        }

#pragma unroll
        for (int nc = 0; nc < 8; ++nc) {
            // ---- GEMM1 chunk: 4 ntiles (2 pairs), K=64; c1 starts at b1 bias ----
            float c1[4][4];
#pragma unroll
            for (int nt = 0; nt < 4; ++nt) {
                const float2 bb = *(const float2*)(b1s + (nc * 32 + nt * 8 + 2 * tq));
                c1[nt][0] = bb.x; c1[nt][1] = bb.y;
                c1[nt][2] = bb.x; c1[nt][3] = bb.y;
            }

            // batched loads (MLP=4) then MMAs, per n-pair
#pragma unroll
            for (int p = 0; p < 2; ++p) {
                uint4 bw[4];
#pragma unroll
                for (int kt = 0; kt < 4; ++kt)
                    bw[kt] = *(const uint4*)(W1f + (((nc * 2 + p) * 4 + kt) * 128 + lane * 4));
#pragma unroll
                for (int kt = 0; kt < 4; ++kt) {
                    mma_bf16(c1[2 * p],     a1f[kt * 4], a1f[kt * 4 + 1], a1f[kt * 4 + 2], a1f[kt * 4 + 3], bw[kt].x, bw[kt].y);
                    mma_bf16(c1[2 * p + 1], a1f[kt * 4], a1f[kt * 4 + 1], a1f[kt * 4 + 2], a1f[kt * 4 + 3], bw[kt].z, bw[kt].w);
                }
            }

            // ---- ELU + pack: C-frags -> GEMM2 A-frags in registers ----
            uint32_t hf[2][4];
#pragma unroll
            for (int nt = 0; nt < 4; ++nt) {
                float v00 = elu_f(c1[nt][0]);
                float v01 = elu_f(c1[nt][1]);
                float v10 = elu_f(c1[nt][2]);
                float v11 = elu_f(c1[nt][3]);
                hf[nt >> 1][(nt & 1) * 2 + 0] = pack_bf16(v00, v01);
                hf[nt >> 1][(nt & 1) * 2 + 1] = pack_bf16(v10, v11);
            }

            // ---- GEMM2 partial: 2 ktiles of 16, batched loads then MMAs ----
#pragma unroll
            for (int ktl = 0; ktl < 2; ++ktl) {
                uint4 bw[4];
#pragma unroll
                for (int n2p = 0; n2p < 4; ++n2p)
                    bw[n2p] = *(const uint4*)(W2f + (((nc * 2 + ktl) * 4 + n2p) * 128 + lane * 4));
#pragma unroll
                for (int n2p = 0; n2p < 4; ++n2p) {
                    mma_bf16(kacc[2 * n2p],     hf[ktl][0], hf[ktl][1], hf[ktl][2], hf[ktl][3], bw[n2p].x, bw[n2p].y);
                    mma_bf16(kacc[2 * n2p + 1], hf[ktl][0], hf[ktl][1], hf[ktl][2], hf[ktl][3], bw[n2p].z, bw[n2p].w);
                }
            }
        } // nc

        // ---- epilogue: k = kacc (bias included); rk4 in fp16x2; repack A1 ----
        const float wk = (s == 1 || s == 2) ? 2.0f : 1.0f;
        const float cn = (s == 2) ? dt : half_dt;
        float yn[8][4];
#pragma unroll
        for (int nt = 0; nt < 8; ++nt) {
            float k0 = kacc[nt][0], k1 = kacc[nt][1];
            float k2 = kacc[nt][2], k3 = kacc[nt][3];

            if (s == 0) {
                rk4h[2 * nt]     = pack_f16(k0, k1);
                rk4h[2 * nt + 1] = pack_f16(k2, k3);
                yn[nt][0] = y0[nt][0] + cn * k0;
                yn[nt][1] = y0[nt][1] + cn * k1;
                yn[nt][2] = y0[nt][2] + cn * k2;
                yn[nt][3] = y0[nt][3] + cn * k3;
            } else if (s < 3) {
                float2 r01 = unpack_f16(rk4h[2 * nt]);
                float2 r23 = unpack_f16(rk4h[2 * nt + 1]);
                r01.x += wk * k0; r01.y += wk * k1;
                r23.x += wk * k2; r23.y += wk * k3;
                rk4h[2 * nt]     = pack_f16(r01.x, r01.y);
                rk4h[2 * nt + 1] = pack_f16(r23.x, r23.y);
                yn[nt][0] = y0[nt][0] + cn * k0;
                yn[nt][1] = y0[nt][1] + cn * k1;
                yn[nt][2] = y0[nt][2] + cn * k2;
                yn[nt][3] = y0[nt][3] + cn * k3;
            } else {
                float2 r01 = unpack_f16(rk4h[2 * nt]);
                float2 r23 = unpack_f16(rk4h[2 * nt + 1]);
                y0[nt][0] += dt6 * (r01.x + k0);
                y0[nt][1] += dt6 * (r01.y + k1);
                y0[nt][2] += dt6 * (r23.x + k2);
                y0[nt][3] += dt6 * (r23.y + k3);
                yn[nt][0] = y0[nt][0]; yn[nt][1] = y0[nt][1];
                yn[nt][2] = y0[nt][2]; yn[nt][3] = y0[nt][3];
            }
        }
#pragma unroll
        for (int kt = 0; kt < 4; ++kt) {
            a1f[kt * 4 + 0] = pack_bf16(yn[2 * kt][0],     yn[2 * kt][1]);
            a1f[kt * 4 + 1] = pack_bf16(yn[2 * kt][2],     yn[2 * kt][3]);
            a1f[kt * 4 + 2] = pack_bf16(yn[2 * kt + 1][0], yn[2 * kt + 1][1]);
            a1f[kt * 4 + 3] = pack_bf16(yn[2 * kt + 1][2], yn[2 * kt + 1][3]);
        }
    } // eval loop

    // ---- write final y0 ----
    {
        float* or0 = out + (size_t)(rbase + g) * D_IN + 2 * tq;
        float* or1 = out + (size_t)(rbase + g + 8) * D_IN + 2 * tq;
#pragma unroll
        for (int nt = 0; nt < 8; ++nt) {
            *(float2*)(or0 + nt * 8) = make_float2(y0[nt][0], y0[nt][1]);
            *(float2*)(or1 + nt * 8) = make_float2(y0[nt][2], y0[nt][3]);
        }
    }
}

extern "C" void kernel_launch(void* const* d_in, const int* in_sizes, int n_in,
                              void* d_out, int out_size) {
    const float* x  = (const float*)d_in[0];
    const float* t  = (const float*)d_in[1];
    const float* W1 = (const float*)d_in[2];
    const float* b1 = (const float*)d_in[3];
    const float* W2 = (const float*)d_in[4];
    const float* b2 = (const float*)d_in[5];
    float* out = (float*)d_out;

    cudaFuncSetAttribute(node_rk4_w12h_kernel,
                         cudaFuncAttributeMaxDynamicSharedMemorySize, SMEM_BYTES);
    node_rk4_w12h_kernel<<<GRID, NT, SMEM_BYTES>>>(x, t, W1, b1, W2, b2, out);
}